// round 17
// baseline (speedup 1.0000x reference)
#include <cuda_runtime.h>
#include <math.h>

// Fixed dataset sizes: N=50000 nodes, E=800000 edges, +N self-loops.
#define NMAX 50000
#define EMAX 800000
#define ETMAX (NMAX + EMAX)
#define SCAN_B 128

// ---------------- static device scratch (no allocations allowed) ---------------
__device__ float  g_bufA[(size_t)NMAX * 256];   // h = in @ W
__device__ float  g_bufB[(size_t)NMAX * 256];   // aggregated output / next input
__device__ float  g_s[NMAX * 4];
__device__ float  g_d[NMAX * 4];
__device__ int    g_src[ETMAX];
__device__ int    g_dst[ETMAX];
__device__ int    g_deg[NMAX];
__device__ int    g_rowstart[NMAX + 1];
__device__ int    g_cursor[NMAX];
__device__ int    g_csr_src[ETMAX];
__device__ int    g_blocksum[SCAN_B];
__device__ int    g_is64;
__device__ double g_sum[256];
__device__ double g_sq[256];
__device__ float  g_scale[256];
__device__ float  g_shift[256];
__device__ double g_psum[64];
__device__ float  g_pmax[64];

// Ordered-int float max; safe for mixed signs when initialized to -inf.
__device__ __forceinline__ void atomicMaxF(float* addr, float v) {
    if (v >= 0.f) atomicMax((int*)addr, __float_as_int(v));
    else          atomicMin((unsigned int*)addr, __float_as_uint(v));
}

// ---------------- edge-index dtype probe + int32 materialization ---------------
__global__ void k_detect(const int* __restrict__ words) {
    if (threadIdx.x == 0) {
        int wide = 1;
        for (int q = 0; q < 128; q++)
            if (words[2 * q + 1] != 0) { wide = 0; break; }
        g_is64 = wide;
    }
}

__global__ void k_cvt(const int* __restrict__ words, int E, int ET) {
    int i = blockIdx.x * blockDim.x + threadIdx.x;
    if (i >= ET) return;
    int sv, dv;
    if (i < E) {
        if (g_is64) { sv = words[2 * (size_t)i]; dv = words[2 * ((size_t)E + i)]; }
        else        { sv = words[i];             dv = words[E + i]; }
    } else {
        sv = dv = i - E;   // appended self-loops
    }
    g_src[i] = sv;
    g_dst[i] = dv;
}

// ---------------- CSR-by-dst build: histogram, 3-phase scan, scatter -----------
__global__ void k_hist(int ET) {
    int i = blockIdx.x * blockDim.x + threadIdx.x;
    if (i < ET) atomicAdd(&g_deg[g_dst[i]], 1);
}

// Phase A: per-block sums over contiguous ranges (wide grid -> wavefronts spread).
__global__ void k_scanA(int Nn) {
    const int b = blockIdx.x, t = threadIdx.x;
    const int C = (Nn + SCAN_B - 1) / SCAN_B;
    const int base = b * C;
    int n = Nn - base; if (n < 0) n = 0; if (n > C) n = C;
    const int per = (C + 255) / 256;
    int lo = base + t * per;
    int hi = min(lo + per, base + n);
    int local = 0;
    for (int i = lo; i < hi; i++) local += g_deg[i];
    __shared__ int ws[8];
    int lane = t & 31, wr = t >> 5;
#pragma unroll
    for (int o = 16; o; o >>= 1) local += __shfl_xor_sync(0xffffffffu, local, o);
    if (lane == 0) ws[wr] = local;
    __syncthreads();
    if (t == 0) {
        int s = 0;
        for (int i = 0; i < 8; i++) s += ws[i];
        g_blocksum[b] = s;
    }
}

// Phase B: exclusive scan of the SCAN_B block sums (single tiny block).
__global__ void k_scanB(int Nn) {
    int t = threadIdx.x;                        // 0..SCAN_B-1 (128)
    __shared__ int wtot[4];
    int v = g_blocksum[t];
    int lane = t & 31, wr = t >> 5;
    int incl = v;
#pragma unroll
    for (int o = 1; o < 32; o <<= 1) {
        int u = __shfl_up_sync(0xffffffffu, incl, o);
        if (lane >= o) incl += u;
    }
    if (lane == 31) wtot[wr] = incl;
    __syncthreads();
    int add = 0;
    for (int i = 0; i < wr; i++) add += wtot[i];
    g_blocksum[t] = add + incl - v;             // exclusive block offset
    if (t == SCAN_B - 1) g_rowstart[Nn] = add + incl;   // grand total
}

// Phase C: block-local scan + block offset -> rowstart/cursor writeback.
__global__ void k_scanC(int Nn) {
    const int b = blockIdx.x, t = threadIdx.x;
    const int C = (Nn + SCAN_B - 1) / SCAN_B;
    const int base = b * C;
    int n = Nn - base; if (n < 0) n = 0; if (n > C) n = C;
    const int per = (C + 255) / 256;
    int lo = base + t * per;
    int hi = min(lo + per, base + n);
    int local = 0;
    for (int i = lo; i < hi; i++) local += g_deg[i];
    __shared__ int wtot[8];
    int lane = t & 31, wr = t >> 5;
    int incl = local;
#pragma unroll
    for (int o = 1; o < 32; o <<= 1) {
        int u = __shfl_up_sync(0xffffffffu, incl, o);
        if (lane >= o) incl += u;
    }
    if (lane == 31) wtot[wr] = incl;
    __syncthreads();
    int add = g_blocksum[b];
    for (int i = 0; i < wr; i++) add += wtot[i];
    int run = add + incl - local;
    for (int i = lo; i < hi; i++) {
        int dg = g_deg[i];
        g_rowstart[i] = run;
        g_cursor[i] = run;
        run += dg;
    }
}

__global__ void k_scatter(int ET) {
    int i = blockIdx.x * blockDim.x + threadIdx.x;
    if (i >= ET) return;
    int slot = atomicAdd(&g_cursor[g_dst[i]], 1);
    g_csr_src[slot] = g_src[i];
}

// ---------------- high-throughput SGEMM ----------------------------------------
// C[M,N] = BNReLU(A)[M,K] @ B[K,N]; row-major; K%16==0, N%TN==0.
template<int TM, int TN>
__global__ void __launch_bounds__((TM/8)*(TN/8))
k_sgemm_opt(const float* __restrict__ A, const float* __restrict__ B,
            float* __restrict__ C, int M, int N, int K,
            const float* __restrict__ bnscale, const float* __restrict__ bnshift) {
    constexpr int BK = 16;
    constexpr int NT = (TM / 8) * (TN / 8);
    constexpr int AV = TM * BK / 4 / NT;
    constexpr int BV = BK * TN / 4 / NT;
    __shared__ float As[2][BK][TM + 4];
    __shared__ float Bs[2][BK][TN];

    const int tid = threadIdx.x;
    const int tx = tid % (TN / 8);
    const int ty = tid / (TN / 8);
    const int rb = blockIdx.y * TM;
    const int cb = blockIdx.x * TN;

    float4 aF[AV], bF[BV];
    float acc[8][8];
#pragma unroll
    for (int i = 0; i < 8; i++)
#pragma unroll
        for (int j = 0; j < 8; j++) acc[i][j] = 0.f;

#pragma unroll
    for (int i = 0; i < AV; i++) {
        const int idx = tid + i * NT;
        const int r = idx / (BK / 4);
        const int c = (idx % (BK / 4)) * 4;
        float4 v = make_float4(0.f, 0.f, 0.f, 0.f);
        if (rb + r < M) v = *(const float4*)(A + (size_t)(rb + r) * K + c);
        if (bnscale) {
            float4 sc = *(const float4*)(bnscale + c);
            float4 sh = *(const float4*)(bnshift + c);
            v.x = fmaxf(fmaf(v.x, sc.x, sh.x), 0.f);
            v.y = fmaxf(fmaf(v.y, sc.y, sh.y), 0.f);
            v.z = fmaxf(fmaf(v.z, sc.z, sh.z), 0.f);
            v.w = fmaxf(fmaf(v.w, sc.w, sh.w), 0.f);
        }
        aF[i] = v;
    }
#pragma unroll
    for (int i = 0; i < BV; i++) {
        const int idx = tid + i * NT;
        const int r = idx / (TN / 4);
        const int c = (idx % (TN / 4)) * 4;
        bF[i] = *(const float4*)(B + (size_t)r * N + cb + c);
    }
#pragma unroll
    for (int i = 0; i < AV; i++) {
        const int idx = tid + i * NT;
        const int r = idx / (BK / 4);
        const int c = (idx % (BK / 4)) * 4;
        As[0][c + 0][r] = aF[i].x;
        As[0][c + 1][r] = aF[i].y;
        As[0][c + 2][r] = aF[i].z;
        As[0][c + 3][r] = aF[i].w;
    }
#pragma unroll
    for (int i = 0; i < BV; i++) {
        const int idx = tid + i * NT;
        const int r = idx / (TN / 4);
        const int c = (idx % (TN / 4)) * 4;
        *(float4*)&Bs[0][r][c] = bF[i];
    }
    __syncthreads();

    int buf = 0;
    for (int k0 = BK; k0 < K; k0 += BK) {
#pragma unroll
        for (int i = 0; i < AV; i++) {
            const int idx = tid + i * NT;
            const int r = idx / (BK / 4);
            const int c = (idx % (BK / 4)) * 4;
            float4 v = make_float4(0.f, 0.f, 0.f, 0.f);
            if (rb + r < M) v = *(const float4*)(A + (size_t)(rb + r) * K + k0 + c);
            if (bnscale) {
                float4 sc = *(const float4*)(bnscale + k0 + c);
                float4 sh = *(const float4*)(bnshift + k0 + c);
                v.x = fmaxf(fmaf(v.x, sc.x, sh.x), 0.f);
                v.y = fmaxf(fmaf(v.y, sc.y, sh.y), 0.f);
                v.z = fmaxf(fmaf(v.z, sc.z, sh.z), 0.f);
                v.w = fmaxf(fmaf(v.w, sc.w, sh.w), 0.f);
            }
            aF[i] = v;
        }
#pragma unroll
        for (int i = 0; i < BV; i++) {
            const int idx = tid + i * NT;
            const int r = idx / (TN / 4);
            const int c = (idx % (TN / 4)) * 4;
            bF[i] = *(const float4*)(B + (size_t)(k0 + r) * N + cb + c);
        }
#pragma unroll
        for (int kk = 0; kk < BK; kk++) {
            float a[8], b[8];
            *(float4*)&a[0] = *(const float4*)&As[buf][kk][ty * 4];
            *(float4*)&a[4] = *(const float4*)&As[buf][kk][TM / 2 + ty * 4];
            *(float4*)&b[0] = *(const float4*)&Bs[buf][kk][tx * 4];
            *(float4*)&b[4] = *(const float4*)&Bs[buf][kk][TN / 2 + tx * 4];
#pragma unroll
            for (int i = 0; i < 8; i++)
#pragma unroll
                for (int j = 0; j < 8; j++)
                    acc[i][j] = fmaf(a[i], b[j], acc[i][j]);
        }
#pragma unroll
        for (int i = 0; i < AV; i++) {
            const int idx = tid + i * NT;
            const int r = idx / (BK / 4);
            const int c = (idx % (BK / 4)) * 4;
            As[buf ^ 1][c + 0][r] = aF[i].x;
            As[buf ^ 1][c + 1][r] = aF[i].y;
            As[buf ^ 1][c + 2][r] = aF[i].z;
            As[buf ^ 1][c + 3][r] = aF[i].w;
        }
#pragma unroll
        for (int i = 0; i < BV; i++) {
            const int idx = tid + i * NT;
            const int r = idx / (TN / 4);
            const int c = (idx % (TN / 4)) * 4;
            *(float4*)&Bs[buf ^ 1][r][c] = bF[i];
        }
        __syncthreads();
        buf ^= 1;
    }
#pragma unroll
    for (int kk = 0; kk < BK; kk++) {
        float a[8], b[8];
        *(float4*)&a[0] = *(const float4*)&As[buf][kk][ty * 4];
        *(float4*)&a[4] = *(const float4*)&As[buf][kk][TM / 2 + ty * 4];
        *(float4*)&b[0] = *(const float4*)&Bs[buf][kk][tx * 4];
        *(float4*)&b[4] = *(const float4*)&Bs[buf][kk][TN / 2 + tx * 4];
#pragma unroll
        for (int i = 0; i < 8; i++)
#pragma unroll
            for (int j = 0; j < 8; j++)
                acc[i][j] = fmaf(a[i], b[j], acc[i][j]);
    }

#pragma unroll
    for (int i = 0; i < 8; i++) {
        int r = rb + (i < 4 ? ty * 4 + i : TM / 2 + ty * 4 + (i - 4));
        if (r < M) {
            float4 v0 = make_float4(acc[i][0], acc[i][1], acc[i][2], acc[i][3]);
            float4 v1 = make_float4(acc[i][4], acc[i][5], acc[i][6], acc[i][7]);
            *(float4*)(C + (size_t)r * N + cb + tx * 4) = v0;
            *(float4*)(C + (size_t)r * N + cb + TN / 2 + tx * 4) = v1;
        }
    }
}

// ---------------- per-(node,head) attention coefficients s,d -------------------
__global__ void k_sd(const float* __restrict__ h, const float* __restrict__ asrc,
                     const float* __restrict__ adst, int Nn, int H) {
    int w = (int)((blockIdx.x * (size_t)blockDim.x + threadIdx.x) >> 5);
    int lane = threadIdx.x & 31;
    if (w >= Nn * H) return;
    int n = w / H, hh = w - n * H;
    const float* hp = h + (size_t)n * H * 64 + hh * 64;
    float x0 = hp[lane], x1 = hp[lane + 32];
    float sv = x0 * asrc[hh * 64 + lane] + x1 * asrc[hh * 64 + lane + 32];
    float dv = x0 * adst[hh * 64 + lane] + x1 * adst[hh * 64 + lane + 32];
#pragma unroll
    for (int o = 16; o; o >>= 1) {
        sv += __shfl_xor_sync(0xffffffffu, sv, o);
        dv += __shfl_xor_sync(0xffffffffu, dv, o);
    }
    if (lane == 0) { g_s[w] = sv; g_d[w] = dv; }
}

// ---------------- fused online-softmax + aggregation (single edge pass) --------
// One warp per destination node; lanes carry (m, s) for their two heads and
// rescale accumulators flash-attention style. No g_m/g_den, no second pass.
__global__ void k_fused256(int Nn) {
    int w = (int)((blockIdx.x * (size_t)blockDim.x + threadIdx.x) >> 5);
    int lane = threadIdx.x & 31;
    if (w >= Nn) return;
    int rs = g_rowstart[w], re = g_rowstart[w + 1];
    float4 d4 = *(const float4*)&g_d[w * 4];
    bool upper = (lane >= 16);                 // head selector for this lane
    float dA = upper ? d4.y : d4.x;            // head h0 = lane>>4
    float dB = upper ? d4.w : d4.z;            // head 2 + h0
    float mA = -3.0e38f, sA = 0.f, mB = -3.0e38f, sB = 0.f;
    float4 acc0 = make_float4(0.f, 0.f, 0.f, 0.f);
    float4 acc1 = make_float4(0.f, 0.f, 0.f, 0.f);
    int src = g_csr_src[rs];                   // >=1 edge per node (self-loop)
    for (int p = rs; p < re; p++) {
        int nxt = (p + 1 < re) ? g_csr_src[p + 1] : 0;
        float4 sv = *(const float4*)&g_s[src * 4];       // warp-uniform load
        float eA = (upper ? sv.y : sv.x) + dA;
        eA = eA > 0.f ? eA : 0.2f * eA;
        float eB = (upper ? sv.w : sv.z) + dB;
        eB = eB > 0.f ? eB : 0.2f * eB;
        float mA2 = fmaxf(mA, eA), mB2 = fmaxf(mB, eB);
        float scA = expf(mA - mA2), scB = expf(mB - mB2);
        float pA = expf(eA - mA2), pB = expf(eB - mB2);
        sA = sA * scA + pA; mA = mA2;
        sB = sB * scB + pB; mB = mB2;
        const float4* hp = (const float4*)(g_bufA + (size_t)src * 256);
        float4 v0 = hp[lane], v1 = hp[lane + 32];
        acc0.x = fmaf(pA, v0.x, acc0.x * scA);
        acc0.y = fmaf(pA, v0.y, acc0.y * scA);
        acc0.z = fmaf(pA, v0.z, acc0.z * scA);
        acc0.w = fmaf(pA, v0.w, acc0.w * scA);
        acc1.x = fmaf(pB, v1.x, acc1.x * scB);
        acc1.y = fmaf(pB, v1.y, acc1.y * scB);
        acc1.z = fmaf(pB, v1.z, acc1.z * scB);
        acc1.w = fmaf(pB, v1.w, acc1.w * scB);
        src = nxt;
    }
    float rA = 1.f / (sA + 1e-16f);
    float rB = 1.f / (sB + 1e-16f);
    acc0.x *= rA; acc0.y *= rA; acc0.z *= rA; acc0.w *= rA;
    acc1.x *= rB; acc1.y *= rB; acc1.z *= rB; acc1.w *= rB;
    float4* op = (float4*)(g_bufB + (size_t)w * 256);
    op[lane] = acc0;
    op[lane + 32] = acc1;
}

__global__ void k_fused64(int Nn) {
    int w = (int)((blockIdx.x * (size_t)blockDim.x + threadIdx.x) >> 5);
    int lane = threadIdx.x & 31;
    if (w >= Nn) return;
    int rs = g_rowstart[w], re = g_rowstart[w + 1];
    float dv = g_d[w];
    float m = -3.0e38f, s = 0.f;
    float2 acc = make_float2(0.f, 0.f);
    int src = g_csr_src[rs];
    for (int p = rs; p < re; p++) {
        int nxt = (p + 1 < re) ? g_csr_src[p + 1] : 0;
        float e = g_s[src] + dv;
        e = e > 0.f ? e : 0.2f * e;
        float m2 = fmaxf(m, e);
        float sc = expf(m - m2);
        float pr = expf(e - m2);
        s = s * sc + pr; m = m2;
        float2 v = ((const float2*)(g_bufA + (size_t)src * 64))[lane];
        acc.x = fmaf(pr, v.x, acc.x * sc);
        acc.y = fmaf(pr, v.y, acc.y * sc);
        src = nxt;
    }
    float r = 1.f / (s + 1e-16f);
    acc.x *= r; acc.y *= r;
    ((float2*)(g_bufB + (size_t)w * 64))[lane] = acc;
}

// ---------------- batchnorm statistics (over x + bias) -------------------------
__global__ void k_bnstats(const float* __restrict__ X, const float* __restrict__ bias,
                          int Nn, int HC) {
    int tid = threadIdx.x;
    int ch = tid & (HC - 1);
    int rpb = blockDim.x / HC;
    int r = blockIdx.x * rpb + tid / HC;
    int stride = gridDim.x * rpb;
    float b = bias[ch];
    float s = 0.f, q = 0.f;
    for (; r < Nn; r += stride) {
        float xv = X[(size_t)r * HC + ch] + b;
        s += xv; q += xv * xv;
    }
    atomicAdd(&g_sum[ch], (double)s);
    atomicAdd(&g_sq[ch], (double)q);
}

__global__ void k_bnfin(const float* __restrict__ gamma, const float* __restrict__ beta,
                        const float* __restrict__ bias, int Nn, int HC) {
    int ch = threadIdx.x;
    if (ch >= HC) return;
    double mu = g_sum[ch] / Nn;
    double var = g_sq[ch] / Nn - mu * mu;
    float sc = (float)((double)gamma[ch] / sqrt(var + 1e-5));
    g_scale[ch] = sc;
    g_shift[ch] = beta[ch] + sc * (bias[ch] - (float)mu);
}

// ---------------- pooling with layer-2 BN+ReLU applied inline ------------------
__global__ void k_initpool() {
    int i = threadIdx.x;
    if (i < 64) { g_pmax[i] = -INFINITY; g_psum[i] = 0.0; }
}

__global__ void k_pool(const float* __restrict__ X, int Nn) {
    int tid = threadIdx.x;
    int ch = tid & 63;
    int rpb = blockDim.x >> 6;
    int r = blockIdx.x * rpb + (tid >> 6);
    int stride = gridDim.x * rpb;
    float sc = g_scale[ch], sh = g_shift[ch];
    float s = 0.f, mx = -INFINITY;
    for (; r < Nn; r += stride) {
        float xv = fmaxf(fmaf(X[(size_t)r * 64 + ch], sc, sh), 0.f);
        s += xv; mx = fmaxf(mx, xv);
    }
    atomicAdd(&g_psum[ch], (double)s);
    atomicMaxF(&g_pmax[ch], mx);
}

// ---------------- classifier head (single block) -------------------------------
__global__ void k_cls(const float* __restrict__ Wc1, const float* __restrict__ bc1,
                      const float* __restrict__ Wc2, const float* __restrict__ bc2,
                      int Nn, float* __restrict__ out) {
    __shared__ float pooled[128];
    __shared__ float z[64];
    int t = threadIdx.x;
    if (t < 64) pooled[t] = (float)(g_psum[t] / Nn);
    else        pooled[t] = g_pmax[t - 64];
    __syncthreads();
    if (t < 64) {
        float acc = bc1[t];
        for (int k = 0; k < 128; k++) acc += pooled[k] * Wc1[k * 64 + t];
        z[t] = fmaxf(acc, 0.f);
    }
    __syncthreads();
    if (t < 2) {
        float acc = bc2[t];
        for (int j = 0; j < 64; j++) acc += z[j] * Wc2[j * 2 + t];
        out[t] = acc;
    }
}

// ---------------- host-side driver ---------------------------------------------
extern "C" void kernel_launch(void* const* d_in, const int* in_sizes, int n_in,
                              void* d_out, int out_size) {
    const float* x   = (const float*)d_in[0];
    const int*   ei  = (const int*)d_in[1];   // int32 or LE-int64; probed on device
    const float* W0  = (const float*)d_in[2];  const float* b0  = (const float*)d_in[3];
    const float* as0 = (const float*)d_in[4];  const float* ad0 = (const float*)d_in[5];
    const float* gm0 = (const float*)d_in[6];  const float* bt0 = (const float*)d_in[7];
    const float* W1  = (const float*)d_in[8];  const float* b1  = (const float*)d_in[9];
    const float* as1 = (const float*)d_in[10]; const float* ad1 = (const float*)d_in[11];
    const float* gm1 = (const float*)d_in[12]; const float* bt1 = (const float*)d_in[13];
    const float* W2  = (const float*)d_in[14]; const float* b2  = (const float*)d_in[15];
    const float* as2 = (const float*)d_in[16]; const float* ad2 = (const float*)d_in[17];
    const float* gm2 = (const float*)d_in[18]; const float* bt2 = (const float*)d_in[19];
    const float* Wc1 = (const float*)d_in[20]; const float* bc1 = (const float*)d_in[21];
    const float* Wc2 = (const float*)d_in[22]; const float* bc2 = (const float*)d_in[23];

    const int Nn = in_sizes[0] / 128;
    const int E  = in_sizes[1] / 2;
    const int ET = E + Nn;

    float* bufA; float* bufB; float* scaleP; float* shiftP;
    void *sumP, *sqP, *psumP, *degP;
    cudaGetSymbolAddress((void**)&bufA, g_bufA);
    cudaGetSymbolAddress((void**)&bufB, g_bufB);
    cudaGetSymbolAddress((void**)&scaleP, g_scale);
    cudaGetSymbolAddress((void**)&shiftP, g_shift);
    cudaGetSymbolAddress(&sumP, g_sum);
    cudaGetSymbolAddress(&sqP, g_sq);
    cudaGetSymbolAddress(&psumP, g_psum);
    cudaGetSymbolAddress(&degP, g_deg);

    // dtype probe, src/dst materialization (+self-loops), CSR-by-dst build
    k_detect<<<1, 32>>>(ei);
    k_cvt<<<(ET + 255) / 256, 256>>>(ei, E, ET);
    cudaMemsetAsync(degP, 0, Nn * sizeof(int), 0);
    k_hist<<<(ET + 255) / 256, 256>>>(ET);
    k_scanA<<<SCAN_B, 256>>>(Nn);
    k_scanB<<<1, SCAN_B>>>(Nn);
    k_scanC<<<SCAN_B, 256>>>(Nn);
    k_scatter<<<(ET + 255) / 256, 256>>>(ET);

    const unsigned nwb = (unsigned)(((long long)Nn * 32 + 255) / 256);  // warp/node

    auto run_layer = [&](const float* in, int K, const float* W, const float* bias,
                         const float* asrc, const float* adst,
                         const float* gamma, const float* beta, int H, bool bnA) {
        const int HC = H * 64;
        const float* sc = bnA ? scaleP : nullptr;
        const float* sh = bnA ? shiftP : nullptr;
        if (HC == 256)
            k_sgemm_opt<128, 128><<<dim3(2, (Nn + 127) / 128), 256>>>(in, W, bufA, Nn, 256, K, sc, sh);
        else
            k_sgemm_opt<128, 64><<<dim3(1, (Nn + 127) / 128), 128>>>(in, W, bufA, Nn, 64, K, sc, sh);
        {
            long long th = (long long)Nn * H * 32;
            k_sd<<<(unsigned)((th + 255) / 256), 256>>>(bufA, asrc, adst, Nn, H);
        }
        if (H == 4) k_fused256<<<nwb, 256>>>(Nn);
        else        k_fused64 <<<nwb, 256>>>(Nn);
        cudaMemsetAsync(sumP, 0, HC * sizeof(double), 0);
        cudaMemsetAsync(sqP, 0, HC * sizeof(double), 0);
        k_bnstats<<<512, 256>>>(bufB, bias, Nn, HC);
        k_bnfin<<<1, 256>>>(gamma, beta, bias, Nn, HC);
        // BN+ReLU is consumed downstream (next GEMM's A-load or k_pool).
    };

    run_layer(x,    128, W0, b0, as0, ad0, gm0, bt0, 4, false);
    run_layer(bufB, 256, W1, b1, as1, ad1, gm1, bt1, 4, true);
    run_layer(bufB, 256, W2, b2, as2, ad2, gm2, bt2, 1, true);

    cudaMemsetAsync(psumP, 0, 64 * sizeof(double), 0);
    k_initpool<<<1, 64>>>();
    k_pool<<<256, 256>>>(bufB, Nn);   // layer-2 BN+ReLU applied inline
    k_cls<<<1, 128>>>(Wc1, bc1, Wc2, bc2, Nn, (float*)d_out);
}